// round 2
// baseline (speedup 1.0000x reference)
#include <cuda_runtime.h>
#include <math.h>
#include <float.h>

// Problem constants
#define BB    8
#define TT    1024
#define FF    256
#define NH    4
#define DKK   64
#define BHH   32      // BB*NH
#define NROWS 8192    // BB*TT

// ---------------- scratch (device globals; no allocations allowed) ----------
static __device__ float g_xn[NROWS * FF];            // layernormed x   (8 MB)
static __device__ float g_q [BHH * TT * DKK];        // Q [bh][t][d]    (8 MB)
static __device__ float g_k [BHH * TT * DKK];        // K [bh][t][d]    (8 MB)
static __device__ float g_v [BHH * TT * DKK];        // V [bh][t][d]    (8 MB)
static __device__ float g_s [(size_t)BHH * TT * TT]; // scores/attn     (128 MB)
static __device__ float g_att[NROWS * FF];           // attn out [b][t][f] (8 MB)

// ---------------- 1) LayerNorm ----------------------------------------------
__global__ void ln_kernel(const float* __restrict__ x, const float* __restrict__ g,
                          const float* __restrict__ b, float* __restrict__ out)
{
    int row = blockIdx.x;
    int tid = threadIdx.x;
    float v = x[row * FF + tid];
    float s = v, sq = v * v;
    __shared__ float rs[8], rq[8];
    #pragma unroll
    for (int o = 16; o > 0; o >>= 1) {
        s  += __shfl_down_sync(0xffffffffu, s,  o);
        sq += __shfl_down_sync(0xffffffffu, sq, o);
    }
    if ((tid & 31) == 0) { rs[tid >> 5] = s; rq[tid >> 5] = sq; }
    __syncthreads();
    if (tid < 32) {
        float a = (tid < 8) ? rs[tid] : 0.f;
        float c = (tid < 8) ? rq[tid] : 0.f;
        #pragma unroll
        for (int o = 4; o > 0; o >>= 1) {
            a += __shfl_down_sync(0xffffffffu, a, o);
            c += __shfl_down_sync(0xffffffffu, c, o);
        }
        if (tid == 0) { rs[0] = a; rq[0] = c; }
    }
    __syncthreads();
    float mean = rs[0] * (1.f / FF);
    float var  = rq[0] * (1.f / FF) - mean * mean;
    float inv  = rsqrtf(fmaxf(var, 0.f) + 1e-5f);
    out[row * FF + tid] = (v - mean) * inv * g[tid] + b[tid];
}

// ---------------- 2) GEMM: C = A(8192x256) @ W(256x256) + bias --------------
// mode 0: scatter to [b][h][t][d] (projection); mode 1: row-major (final out)
// Tile 128x64, BK=16, 256 threads, 8x4 microtile.
__global__ void gemm_kernel(const float* __restrict__ A, const float* __restrict__ W,
                            const float* __restrict__ bias, float* __restrict__ C,
                            int mode)
{
    __shared__ float As[16][132];   // [k][m], padded (keeps 16B alignment: 132*4=528)
    __shared__ float Ws[16][64];    // [k][n]
    int tid = threadIdx.x;
    int tx = tid & 15, ty = tid >> 4;
    int m0 = blockIdx.y * 128, n0 = blockIdx.x * 64;

    float acc[8][4];
    #pragma unroll
    for (int i = 0; i < 8; i++)
        #pragma unroll
        for (int j = 0; j < 4; j++) acc[i][j] = 0.f;

    int lm  = tid >> 1;
    int lkg = (tid & 1) * 8;
    int wk  = tid >> 4, wc = (tid & 15) * 4;

    for (int k0 = 0; k0 < FF; k0 += 16) {
        const float* asrc = A + (size_t)(m0 + lm) * FF + k0 + lkg;
        float4 v0 = *(const float4*)(asrc);
        float4 v1 = *(const float4*)(asrc + 4);
        As[lkg + 0][lm] = v0.x; As[lkg + 1][lm] = v0.y;
        As[lkg + 2][lm] = v0.z; As[lkg + 3][lm] = v0.w;
        As[lkg + 4][lm] = v1.x; As[lkg + 5][lm] = v1.y;
        As[lkg + 6][lm] = v1.z; As[lkg + 7][lm] = v1.w;
        *(float4*)&Ws[wk][wc] = *(const float4*)(W + (size_t)(k0 + wk) * FF + n0 + wc);
        __syncthreads();
        #pragma unroll
        for (int k = 0; k < 16; k++) {
            float4 a0 = *(const float4*)&As[k][ty * 8];
            float4 a1 = *(const float4*)&As[k][ty * 8 + 4];
            float4 w0 = *(const float4*)&Ws[k][tx * 4];
            float a[8] = {a0.x, a0.y, a0.z, a0.w, a1.x, a1.y, a1.z, a1.w};
            float w[4] = {w0.x, w0.y, w0.z, w0.w};
            #pragma unroll
            for (int i = 0; i < 8; i++)
                #pragma unroll
                for (int j = 0; j < 4; j++)
                    acc[i][j] = fmaf(a[i], w[j], acc[i][j]);
        }
        __syncthreads();
    }

    float bi[4];
    #pragma unroll
    for (int j = 0; j < 4; j++) bi[j] = bias[n0 + tx * 4 + j];

    #pragma unroll
    for (int i = 0; i < 8; i++) {
        int r = m0 + ty * 8 + i;
        float4 o;
        o.x = acc[i][0] + bi[0]; o.y = acc[i][1] + bi[1];
        o.z = acc[i][2] + bi[2]; o.w = acc[i][3] + bi[3];
        if (mode == 0) {
            int c = n0 + tx * 4;
            int h = c >> 6, d = c & 63;
            int b_ = r >> 10, t = r & 1023;
            *(float4*)&C[(((size_t)(b_ * NH + h) * TT + t) * DKK) + d] = o;
        } else {
            *(float4*)&C[(size_t)r * FF + n0 + tx * 4] = o;
        }
    }
}

// ---------------- 3) S[bh][q][t] = Q . K  (batched, K=64 full) --------------
// Tile 128(q) x 64(t), 256 threads, 8x4 microtile.
__global__ void qk_kernel(const float* __restrict__ Q, const float* __restrict__ K,
                          float* __restrict__ S)
{
    __shared__ float Qs[64][128];   // [d][q]  32 KB
    __shared__ float Ks[64][64];    // [d][t]  16 KB
    int tid = threadIdx.x;
    int bh = blockIdx.z;
    int q0 = blockIdx.y * 128, t0 = blockIdx.x * 64;
    {
        int q = tid >> 1, dg = (tid & 1) * 32;
        const float* src = Q + ((size_t)bh * TT + q0 + q) * DKK + dg;
        #pragma unroll
        for (int j = 0; j < 8; j++) {
            float4 vv = *(const float4*)(src + j * 4);
            Qs[dg + j * 4 + 0][q] = vv.x; Qs[dg + j * 4 + 1][q] = vv.y;
            Qs[dg + j * 4 + 2][q] = vv.z; Qs[dg + j * 4 + 3][q] = vv.w;
        }
        int t = tid >> 2, dg2 = (tid & 3) * 16;
        const float* ks = K + ((size_t)bh * TT + t0 + t) * DKK + dg2;
        #pragma unroll
        for (int j = 0; j < 4; j++) {
            float4 vv = *(const float4*)(ks + j * 4);
            Ks[dg2 + j * 4 + 0][t] = vv.x; Ks[dg2 + j * 4 + 1][t] = vv.y;
            Ks[dg2 + j * 4 + 2][t] = vv.z; Ks[dg2 + j * 4 + 3][t] = vv.w;
        }
    }
    __syncthreads();
    int tx = tid & 15, ty = tid >> 4;
    float acc[8][4];
    #pragma unroll
    for (int i = 0; i < 8; i++)
        #pragma unroll
        for (int j = 0; j < 4; j++) acc[i][j] = 0.f;

    #pragma unroll 16
    for (int d = 0; d < 64; d++) {
        float4 a0 = *(const float4*)&Qs[d][ty * 8];
        float4 a1 = *(const float4*)&Qs[d][ty * 8 + 4];
        float4 b0 = *(const float4*)&Ks[d][tx * 4];
        float a[8] = {a0.x, a0.y, a0.z, a0.w, a1.x, a1.y, a1.z, a1.w};
        float w[4] = {b0.x, b0.y, b0.z, b0.w};
        #pragma unroll
        for (int i = 0; i < 8; i++)
            #pragma unroll
            for (int j = 0; j < 4; j++)
                acc[i][j] = fmaf(a[i], w[j], acc[i][j]);
    }
    float* dst = S + (size_t)bh * TT * TT + (size_t)q0 * TT + t0;
    #pragma unroll
    for (int i = 0; i < 8; i++) {
        float4 o = make_float4(acc[i][0], acc[i][1], acc[i][2], acc[i][3]);
        *(float4*)&dst[(size_t)(ty * 8 + i) * TT + tx * 4] = o;
    }
}

// ---------------- 4) S[bh][q][t] += q[bh][q][:] . pos_k[q][t][:] ------------
// CTA = (q, 128-t block), covers all 32 (b,h): pos_k read exactly once.
__global__ void bias_kernel(const float* __restrict__ Q, const float* __restrict__ PK,
                            float* __restrict__ S)
{
    __shared__ float Qs[32][64];    //  8 KB
    __shared__ float Ps[128][65];   // ~33 KB (pad 65 -> conflict-free strided reads)
    int tid = threadIdx.x;
    int q  = blockIdx.y;
    int t0 = blockIdx.x * 128;
    {
        int bh = tid >> 3, dg = (tid & 7) * 8;
        const float* src = Q + ((size_t)bh * TT + q) * DKK + dg;
        *(float4*)&Qs[bh][dg]     = *(const float4*)(src);
        *(float4*)&Qs[bh][dg + 4] = *(const float4*)(src + 4);
    }
    {
        const float* base = PK + ((size_t)q * TT + t0) * DKK;
        #pragma unroll
        for (int j = 0; j < 8; j++) {
            int f4 = tid + 256 * j;          // 0..2047 float4s
            int rr = f4 >> 4;
            int cc = (f4 & 15) * 4;
            float4 vv = *(const float4*)(base + (size_t)rr * DKK + cc);
            Ps[rr][cc + 0] = vv.x; Ps[rr][cc + 1] = vv.y;
            Ps[rr][cc + 2] = vv.z; Ps[rr][cc + 3] = vv.w;
        }
    }
    __syncthreads();
    int bhg = tid >> 5;       // 0..7 -> 4 bh each
    int ts  = tid & 31;
    int bh0 = bhg * 4;
    float acc[4][4];
    #pragma unroll
    for (int a = 0; a < 4; a++)
        #pragma unroll
        for (int b = 0; b < 4; b++) acc[a][b] = 0.f;

    for (int dc = 0; dc < 64; dc += 8) {
        float qr[4][8];
        #pragma unroll
        for (int bb = 0; bb < 4; bb++)
            #pragma unroll
            for (int dd = 0; dd < 8; dd++)
                qr[bb][dd] = Qs[bh0 + bb][dc + dd];
        #pragma unroll
        for (int i = 0; i < 4; i++) {
            int trow = ts + 32 * i;
            float p[8];
            #pragma unroll
            for (int dd = 0; dd < 8; dd++) p[dd] = Ps[trow][dc + dd];
            #pragma unroll
            for (int bb = 0; bb < 4; bb++) {
                float a = acc[bb][i];
                #pragma unroll
                for (int dd = 0; dd < 8; dd++) a = fmaf(qr[bb][dd], p[dd], a);
                acc[bb][i] = a;
            }
        }
    }
    #pragma unroll
    for (int bb = 0; bb < 4; bb++) {
        size_t base = (size_t)(bh0 + bb) * TT * TT + (size_t)q * TT + t0;
        #pragma unroll
        for (int i = 0; i < 4; i++)
            S[base + ts + 32 * i] += acc[bb][i];
    }
}

// ---------------- 5) masked softmax over t, in place ------------------------
__global__ void softmax_kernel(float* __restrict__ S, const int* __restrict__ mask)
{
    int row = blockIdx.x;              // bh*T + q
    int bh = row >> 10, q = row & 1023;
    int b_ = bh >> 2;
    const int* mrow = mask + ((size_t)b_ * TT + q) * TT;
    float* srow = S + (size_t)row * TT;
    int tid = threadIdx.x;

    float v[4]; int mk[4];
    float mx = -FLT_MAX;
    #pragma unroll
    for (int i = 0; i < 4; i++) {
        int t = tid + 256 * i;
        mk[i] = mrow[t];
        v[i] = (mk[i] == 0) ? -FLT_MAX : srow[t] * 0.125f;
        mx = fmaxf(mx, v[i]);
    }
    __shared__ float red[8];
    #pragma unroll
    for (int o = 16; o > 0; o >>= 1) mx = fmaxf(mx, __shfl_xor_sync(0xffffffffu, mx, o));
    if ((tid & 31) == 0) red[tid >> 5] = mx;
    __syncthreads();
    mx = red[0];
    #pragma unroll
    for (int w = 1; w < 8; w++) mx = fmaxf(mx, red[w]);
    __syncthreads();

    float p[4]; float sum = 0.f;
    #pragma unroll
    for (int i = 0; i < 4; i++) {
        p[i] = (mk[i] == 0) ? 0.f : __expf(v[i] - mx);
        sum += p[i];
    }
    #pragma unroll
    for (int o = 16; o > 0; o >>= 1) sum += __shfl_xor_sync(0xffffffffu, sum, o);
    if ((tid & 31) == 0) red[tid >> 5] = sum;
    __syncthreads();
    sum = red[0];
    #pragma unroll
    for (int w = 1; w < 8; w++) sum += red[w];
    float inv = (sum > 0.f) ? (1.f / sum) : 0.f;
    #pragma unroll
    for (int i = 0; i < 4; i++)
        srow[tid + 256 * i] = p[i] * inv;
}

// ---------------- 6) O_att[b][q][h*64+d] = sum_t attn * V ------------------
// Tile 128(q) x 64(d), BK=32 over t.
__global__ void av_kernel(const float* __restrict__ P, const float* __restrict__ V,
                          float* __restrict__ O)
{
    __shared__ float Ps[32][132];   // [t][q], padded (132*4=528, 16B aligned rows)
    __shared__ float Vs[32][64];    // [t][d]
    int tid = threadIdx.x;
    int q0 = blockIdx.x * 128;
    int bh = blockIdx.y;
    int b_ = bh >> 2, h = bh & 3;
    int tx = tid & 15, ty = tid >> 4;
    float acc[8][4];
    #pragma unroll
    for (int i = 0; i < 8; i++)
        #pragma unroll
        for (int j = 0; j < 4; j++) acc[i][j] = 0.f;

    const float* Pb = P + (size_t)bh * TT * TT;
    const float* Vb = V + (size_t)bh * TT * DKK;

    for (int t0 = 0; t0 < TT; t0 += 32) {
        int q = tid >> 1, tg = (tid & 1) * 16;
        const float* src = Pb + (size_t)(q0 + q) * TT + t0 + tg;
        #pragma unroll
        for (int j = 0; j < 4; j++) {
            float4 vv = *(const float4*)(src + j * 4);
            Ps[tg + j * 4 + 0][q] = vv.x; Ps[tg + j * 4 + 1][q] = vv.y;
            Ps[tg + j * 4 + 2][q] = vv.z; Ps[tg + j * 4 + 3][q] = vv.w;
        }
        #pragma unroll
        for (int j = 0; j < 2; j++) {
            int f4i = tid + 256 * j;
            int rr = f4i >> 4, cc = (f4i & 15) * 4;
            *(float4*)&Vs[rr][cc] = *(const float4*)(Vb + (size_t)(t0 + rr) * DKK + cc);
        }
        __syncthreads();
        #pragma unroll 8
        for (int t = 0; t < 32; t++) {
            float4 a0 = *(const float4*)&Ps[t][ty * 8];
            float4 a1 = *(const float4*)&Ps[t][ty * 8 + 4];
            float4 b0 = *(const float4*)&Vs[t][tx * 4];
            float a[8] = {a0.x, a0.y, a0.z, a0.w, a1.x, a1.y, a1.z, a1.w};
            float w[4] = {b0.x, b0.y, b0.z, b0.w};
            #pragma unroll
            for (int i = 0; i < 8; i++)
                #pragma unroll
                for (int j = 0; j < 4; j++)
                    acc[i][j] = fmaf(a[i], w[j], acc[i][j]);
        }
        __syncthreads();
    }
    #pragma unroll
    for (int i = 0; i < 8; i++) {
        int q = q0 + ty * 8 + i;
        float4 o = make_float4(acc[i][0], acc[i][1], acc[i][2], acc[i][3]);
        *(float4*)&O[((size_t)b_ * TT + q) * FF + h * DKK + tx * 4] = o;
    }
}

// ---------------- launch -----------------------------------------------------
extern "C" void kernel_launch(void* const* d_in, const int* in_sizes, int n_in,
                              void* d_out, int out_size)
{
    (void)in_sizes; (void)n_in; (void)out_size;
    const float* x     = (const float*)d_in[0];
    const float* q_in  = (const float*)d_in[1];
    const float* pos_k = (const float*)d_in[2];
    const int*   mask  = (const int*)  d_in[3];
    const float* ln_g  = (const float*)d_in[4];
    const float* ln_b  = (const float*)d_in[5];
    const float* Wq    = (const float*)d_in[6];
    const float* bq    = (const float*)d_in[7];
    const float* Wk    = (const float*)d_in[8];
    const float* bk    = (const float*)d_in[9];
    const float* Wv    = (const float*)d_in[10];
    const float* bv    = (const float*)d_in[11];
    const float* Wo    = (const float*)d_in[12];
    const float* bo    = (const float*)d_in[13];
    float* out = (float*)d_out;

    float *p_xn, *p_q, *p_k, *p_v, *p_s, *p_att;
    cudaGetSymbolAddress((void**)&p_xn,  g_xn);
    cudaGetSymbolAddress((void**)&p_q,   g_q);
    cudaGetSymbolAddress((void**)&p_k,   g_k);
    cudaGetSymbolAddress((void**)&p_v,   g_v);
    cudaGetSymbolAddress((void**)&p_s,   g_s);
    cudaGetSymbolAddress((void**)&p_att, g_att);

    ln_kernel<<<NROWS, 256>>>(x, ln_g, ln_b, p_xn);

    dim3 ggemm(FF / 64, NROWS / 128);
    gemm_kernel<<<ggemm, 256>>>(q_in, Wq, bq, p_q, 0);
    gemm_kernel<<<ggemm, 256>>>(p_xn, Wk, bk, p_k, 0);
    gemm_kernel<<<ggemm, 256>>>(p_xn, Wv, bv, p_v, 0);

    dim3 gqk(TT / 64, TT / 128, BHH);
    qk_kernel<<<gqk, 256>>>(p_q, p_k, p_s);

    dim3 gbias(TT / 128, TT);
    bias_kernel<<<gbias, 256>>>(p_q, pos_k, p_s);

    softmax_kernel<<<BHH * TT, 256>>>(p_s, mask);

    dim3 gav(TT / 128, BHH);
    av_kernel<<<gav, 256>>>(p_s, p_v, p_att);

    gemm_kernel<<<ggemm, 256>>>(p_att, Wo, bo, out, 1);
}

// round 3
// speedup vs baseline: 1.3203x; 1.3203x over previous
#include <cuda_runtime.h>
#include <math.h>
#include <float.h>

#define BB    8
#define TT    1024
#define FF    256
#define NH    4
#define DKK   64
#define BHH   32
#define NROWS 8192

// ---------------- scratch ----------------------------------------------------
static __device__ float g_xn[NROWS * FF];
static __device__ float g_q [BHH * TT * DKK];
static __device__ float g_k [BHH * TT * DKK];
static __device__ float g_v [BHH * TT * DKK];
static __device__ float g_s [(size_t)BHH * TT * TT];
static __device__ float g_att[NROWS * FF];

// ---------------- tf32 mma helpers -------------------------------------------
__device__ __forceinline__ unsigned f2tf(float x) {
    unsigned r; asm("cvt.rna.tf32.f32 %0, %1;" : "=r"(r) : "f"(x)); return r;
}
__device__ __forceinline__ void mma8(float* d, const unsigned* a, const unsigned* b, const float* c) {
    asm volatile("mma.sync.aligned.m16n8k8.row.col.f32.tf32.tf32.f32 "
                 "{%0,%1,%2,%3}, {%4,%5,%6,%7}, {%8,%9}, {%10,%11,%12,%13};"
                 : "=f"(d[0]), "=f"(d[1]), "=f"(d[2]), "=f"(d[3])
                 : "r"(a[0]), "r"(a[1]), "r"(a[2]), "r"(a[3]),
                   "r"(b[0]), "r"(b[1]),
                   "f"(c[0]), "f"(c[1]), "f"(c[2]), "f"(c[3]));
}

// ---------------- 1) LayerNorm -----------------------------------------------
__global__ void ln_kernel(const float* __restrict__ x, const float* __restrict__ g,
                          const float* __restrict__ b, float* __restrict__ out)
{
    int row = blockIdx.x;
    int tid = threadIdx.x;
    float v = x[row * FF + tid];
    float s = v, sq = v * v;
    __shared__ float rs[8], rq[8];
    #pragma unroll
    for (int o = 16; o > 0; o >>= 1) {
        s  += __shfl_down_sync(0xffffffffu, s,  o);
        sq += __shfl_down_sync(0xffffffffu, sq, o);
    }
    if ((tid & 31) == 0) { rs[tid >> 5] = s; rq[tid >> 5] = sq; }
    __syncthreads();
    if (tid < 32) {
        float a = (tid < 8) ? rs[tid] : 0.f;
        float c = (tid < 8) ? rq[tid] : 0.f;
        #pragma unroll
        for (int o = 4; o > 0; o >>= 1) {
            a += __shfl_down_sync(0xffffffffu, a, o);
            c += __shfl_down_sync(0xffffffffu, c, o);
        }
        if (tid == 0) { rs[0] = a; rq[0] = c; }
    }
    __syncthreads();
    float mean = rs[0] * (1.f / FF);
    float var  = rq[0] * (1.f / FF) - mean * mean;
    float inv  = rsqrtf(fmaxf(var, 0.f) + 1e-5f);
    out[row * FF + tid] = (v - mean) * inv * g[tid] + b[tid];
}

// ---------------- 2) tf32 GEMM: C = A(8192x256) @ W(256x256) + bias ----------
// Block 128x128, 8 warps (2m x 4n), warp tile 64x32. mode0: scatter [bh][t][d].
__global__ void __launch_bounds__(256)
gemm_tf32(const float* __restrict__ A, const float* __restrict__ W,
          const float* __restrict__ bias, float* __restrict__ C, int mode)
{
    __shared__ unsigned As[128][36];
    __shared__ unsigned Ws[32][136];
    int tid = threadIdx.x, w = tid >> 5, l = tid & 31, g = l >> 2, t4 = l & 3;
    int m0 = blockIdx.y * 128, n0 = blockIdx.x * 128;
    int wm = (w >> 2) * 64, wn = (w & 3) * 32;

    float acc[4][4][4];
    #pragma unroll
    for (int i = 0; i < 4; i++)
        #pragma unroll
        for (int j = 0; j < 4; j++)
            #pragma unroll
            for (int e = 0; e < 4; e++) acc[i][j][e] = 0.f;

    int ar = tid >> 1, ak = (tid & 1) * 16;
    int wr = tid >> 3, wc = (tid & 7) * 16;

    for (int k0 = 0; k0 < FF; k0 += 32) {
        const float* ap = A + (size_t)(m0 + ar) * FF + k0 + ak;
        #pragma unroll
        for (int j = 0; j < 4; j++) {
            float4 v = *(const float4*)(ap + j * 4);
            As[ar][ak + j*4 + 0] = f2tf(v.x); As[ar][ak + j*4 + 1] = f2tf(v.y);
            As[ar][ak + j*4 + 2] = f2tf(v.z); As[ar][ak + j*4 + 3] = f2tf(v.w);
        }
        const float* wp = W + (size_t)(k0 + wr) * FF + n0 + wc;
        #pragma unroll
        for (int j = 0; j < 4; j++) {
            float4 v = *(const float4*)(wp + j * 4);
            Ws[wr][wc + j*4 + 0] = f2tf(v.x); Ws[wr][wc + j*4 + 1] = f2tf(v.y);
            Ws[wr][wc + j*4 + 2] = f2tf(v.z); Ws[wr][wc + j*4 + 3] = f2tf(v.w);
        }
        __syncthreads();
        #pragma unroll
        for (int ks = 0; ks < 4; ks++) {
            unsigned af[4][4], bf[4][2];
            #pragma unroll
            for (int mi = 0; mi < 4; mi++) {
                int r = wm + mi * 16;
                af[mi][0] = As[r + g    ][ks*8 + t4];
                af[mi][1] = As[r + g + 8][ks*8 + t4];
                af[mi][2] = As[r + g    ][ks*8 + t4 + 4];
                af[mi][3] = As[r + g + 8][ks*8 + t4 + 4];
            }
            #pragma unroll
            for (int ni = 0; ni < 4; ni++) {
                int c = wn + ni * 8 + g;
                bf[ni][0] = Ws[ks*8 + t4    ][c];
                bf[ni][1] = Ws[ks*8 + t4 + 4][c];
            }
            #pragma unroll
            for (int mi = 0; mi < 4; mi++)
                #pragma unroll
                for (int ni = 0; ni < 4; ni++)
                    mma8(acc[mi][ni], af[mi], bf[ni], acc[mi][ni]);
        }
        __syncthreads();
    }

    #pragma unroll
    for (int mi = 0; mi < 4; mi++) {
        #pragma unroll
        for (int ni = 0; ni < 4; ni++) {
            int col = n0 + wn + ni * 8 + 2 * t4;
            float b0 = bias[col], b1 = bias[col + 1];
            int r0 = m0 + wm + mi * 16 + g;
            float2 o0 = make_float2(acc[mi][ni][0] + b0, acc[mi][ni][1] + b1);
            float2 o1 = make_float2(acc[mi][ni][2] + b0, acc[mi][ni][3] + b1);
            if (mode == 0) {
                int h = col >> 6, d = col & 63;
                int b_ = r0 >> 10, t = r0 & 1023;
                *(float2*)&C[(((size_t)(b_*NH + h) * TT + t) * DKK) + d] = o0;
                int r1 = r0 + 8; b_ = r1 >> 10; t = r1 & 1023;
                *(float2*)&C[(((size_t)(b_*NH + h) * TT + t) * DKK) + d] = o1;
            } else {
                *(float2*)&C[(size_t)r0 * FF + col] = o0;
                *(float2*)&C[(size_t)(r0 + 8) * FF + col] = o1;
            }
        }
    }
}

// ---------------- 3) tf32 QK^T: S[bh][q][t] ----------------------------------
// Block 128q x 128t, K=64. Dynamic smem (~70 KB).
__global__ void __launch_bounds__(256)
qk_tf32(const float* __restrict__ Q, const float* __restrict__ K, float* __restrict__ S)
{
    extern __shared__ unsigned qksm[];
    unsigned* Qs = qksm;              // [128][68]
    unsigned* Ks = qksm + 128 * 68;   // [128][68]
    int tid = threadIdx.x, w = tid >> 5, l = tid & 31, g = l >> 2, t4 = l & 3;
    int bh = blockIdx.z, q0 = blockIdx.y * 128, t0 = blockIdx.x * 128;
    int wm = (w >> 2) * 64, wn = (w & 3) * 32;

    {
        int r = tid >> 1, dg = (tid & 1) * 32;
        const float* qp = Q + ((size_t)bh * TT + q0 + r) * DKK + dg;
        const float* kp = K + ((size_t)bh * TT + t0 + r) * DKK + dg;
        #pragma unroll
        for (int j = 0; j < 8; j++) {
            float4 v = *(const float4*)(qp + j * 4);
            Qs[r*68 + dg + j*4 + 0] = f2tf(v.x); Qs[r*68 + dg + j*4 + 1] = f2tf(v.y);
            Qs[r*68 + dg + j*4 + 2] = f2tf(v.z); Qs[r*68 + dg + j*4 + 3] = f2tf(v.w);
            float4 u = *(const float4*)(kp + j * 4);
            Ks[r*68 + dg + j*4 + 0] = f2tf(u.x); Ks[r*68 + dg + j*4 + 1] = f2tf(u.y);
            Ks[r*68 + dg + j*4 + 2] = f2tf(u.z); Ks[r*68 + dg + j*4 + 3] = f2tf(u.w);
        }
    }
    __syncthreads();

    float acc[4][4][4];
    #pragma unroll
    for (int i = 0; i < 4; i++)
        #pragma unroll
        for (int j = 0; j < 4; j++)
            #pragma unroll
            for (int e = 0; e < 4; e++) acc[i][j][e] = 0.f;

    #pragma unroll
    for (int ks = 0; ks < 8; ks++) {
        unsigned af[4][4], bf[4][2];
        #pragma unroll
        for (int mi = 0; mi < 4; mi++) {
            int r = wm + mi * 16;
            af[mi][0] = Qs[(r + g    )*68 + ks*8 + t4];
            af[mi][1] = Qs[(r + g + 8)*68 + ks*8 + t4];
            af[mi][2] = Qs[(r + g    )*68 + ks*8 + t4 + 4];
            af[mi][3] = Qs[(r + g + 8)*68 + ks*8 + t4 + 4];
        }
        #pragma unroll
        for (int ni = 0; ni < 4; ni++) {
            int c = wn + ni * 8 + g;
            bf[ni][0] = Ks[c*68 + ks*8 + t4];
            bf[ni][1] = Ks[c*68 + ks*8 + t4 + 4];
        }
        #pragma unroll
        for (int mi = 0; mi < 4; mi++)
            #pragma unroll
            for (int ni = 0; ni < 4; ni++)
                mma8(acc[mi][ni], af[mi], bf[ni], acc[mi][ni]);
    }

    float* dst = S + (size_t)bh * TT * TT;
    #pragma unroll
    for (int mi = 0; mi < 4; mi++)
        #pragma unroll
        for (int ni = 0; ni < 4; ni++) {
            int r0 = q0 + wm + mi * 16 + g;
            int col = t0 + wn + ni * 8 + 2 * t4;
            *(float2*)&dst[(size_t)r0 * TT + col] = make_float2(acc[mi][ni][0], acc[mi][ni][1]);
            *(float2*)&dst[(size_t)(r0 + 8) * TT + col] = make_float2(acc[mi][ni][2], acc[mi][ni][3]);
        }
}

// ---------------- 4) fused bias + mask + softmax -----------------------------
// CTA per q. Bias = [32bh x 64d] @ [64d x 1024t] via tf32 mma (pos_k read once),
// then each warp owns 4 bh rows: combine with S, mask, softmax, write attn.
__global__ void __launch_bounds__(256)
bsm_kernel(const float* __restrict__ Qg, const float* __restrict__ PK,
           const int* __restrict__ mask, float* __restrict__ S)
{
    extern __shared__ float sm[];
    float*    Ss = sm;                                 // [32][1026]
    unsigned* Qs = (unsigned*)(sm + 32 * 1026);        // [32][68]
    unsigned* Ps = Qs + 32 * 68;                       // [128][68]
    int tid = threadIdx.x, w = tid >> 5, l = tid & 31, g = l >> 2, t4 = l & 3;
    int q = blockIdx.x;

    {   // load all 32 q-vectors (tf32)
        int bh = tid >> 3, dg = (tid & 7) * 8;
        const float* src = Qg + ((size_t)bh * TT + q) * DKK + dg;
        float4 v0 = *(const float4*)(src);
        float4 v1 = *(const float4*)(src + 4);
        Qs[bh*68 + dg + 0] = f2tf(v0.x); Qs[bh*68 + dg + 1] = f2tf(v0.y);
        Qs[bh*68 + dg + 2] = f2tf(v0.z); Qs[bh*68 + dg + 3] = f2tf(v0.w);
        Qs[bh*68 + dg + 4] = f2tf(v1.x); Qs[bh*68 + dg + 5] = f2tf(v1.y);
        Qs[bh*68 + dg + 6] = f2tf(v1.z); Qs[bh*68 + dg + 7] = f2tf(v1.w);
    }
    __syncthreads();

    // ---- bias GEMM in 8 chunks of 128 t ----
    for (int c = 0; c < 8; c++) {
        int t0 = c * 128;
        const float* base = PK + ((size_t)q * TT + t0) * DKK;
        #pragma unroll
        for (int j = 0; j < 8; j++) {
            int f4 = tid + 256 * j;
            int rr = f4 >> 4, cc = (f4 & 15) * 4;
            float4 v = *(const float4*)(base + (size_t)rr * DKK + cc);
            Ps[rr*68 + cc + 0] = f2tf(v.x); Ps[rr*68 + cc + 1] = f2tf(v.y);
            Ps[rr*68 + cc + 2] = f2tf(v.z); Ps[rr*68 + cc + 3] = f2tf(v.w);
        }
        __syncthreads();

        float acc[2][2][4];
        #pragma unroll
        for (int mi = 0; mi < 2; mi++)
            #pragma unroll
            for (int ni = 0; ni < 2; ni++)
                #pragma unroll
                for (int e = 0; e < 4; e++) acc[mi][ni][e] = 0.f;

        #pragma unroll
        for (int ks = 0; ks < 8; ks++) {
            unsigned af[2][4], bf[2][2];
            #pragma unroll
            for (int mi = 0; mi < 2; mi++) {
                int r = mi * 16;
                af[mi][0] = Qs[(r + g    )*68 + ks*8 + t4];
                af[mi][1] = Qs[(r + g + 8)*68 + ks*8 + t4];
                af[mi][2] = Qs[(r + g    )*68 + ks*8 + t4 + 4];
                af[mi][3] = Qs[(r + g + 8)*68 + ks*8 + t4 + 4];
            }
            #pragma unroll
            for (int ni = 0; ni < 2; ni++) {
                int cn = w * 16 + ni * 8 + g;
                bf[ni][0] = Ps[cn*68 + ks*8 + t4];
                bf[ni][1] = Ps[cn*68 + ks*8 + t4 + 4];
            }
            #pragma unroll
            for (int mi = 0; mi < 2; mi++)
                #pragma unroll
                for (int ni = 0; ni < 2; ni++)
                    mma8(acc[mi][ni], af[mi], bf[ni], acc[mi][ni]);
        }
        #pragma unroll
        for (int mi = 0; mi < 2; mi++)
            #pragma unroll
            for (int ni = 0; ni < 2; ni++) {
                int row = mi * 16 + g;
                int col = t0 + w * 16 + ni * 8 + 2 * t4;
                Ss[row * 1026 + col]       = acc[mi][ni][0];
                Ss[row * 1026 + col + 1]   = acc[mi][ni][1];
                Ss[(row + 8) * 1026 + col]     = acc[mi][ni][2];
                Ss[(row + 8) * 1026 + col + 1] = acc[mi][ni][3];
            }
        __syncthreads();
    }

    // ---- combine + mask + softmax: warp w owns bh = 4w..4w+3 ----
    int bh0 = w * 4;
    const int* mrow = mask + ((size_t)w * TT + q) * TT;
    float mx[4] = {-FLT_MAX, -FLT_MAX, -FLT_MAX, -FLT_MAX};
    #pragma unroll
    for (int bb = 0; bb < 4; bb++) {
        int bh = bh0 + bb;
        const float* srow = S + (size_t)bh * TT * TT + (size_t)q * TT;
        for (int i = 0; i < 32; i++) {
            int t = l + 32 * i;
            float v = (mrow[t] == 0) ? -FLT_MAX
                                     : (srow[t] + Ss[bh * 1026 + t]) * 0.125f;
            Ss[bh * 1026 + t] = v;
            mx[bb] = fmaxf(mx[bb], v);
        }
    }
    #pragma unroll
    for (int bb = 0; bb < 4; bb++)
        #pragma unroll
        for (int o = 16; o > 0; o >>= 1)
            mx[bb] = fmaxf(mx[bb], __shfl_xor_sync(0xffffffffu, mx[bb], o));

    float sum[4] = {0.f, 0.f, 0.f, 0.f};
    #pragma unroll
    for (int bb = 0; bb < 4; bb++) {
        int bh = bh0 + bb;
        for (int i = 0; i < 32; i++) {
            int t = l + 32 * i;
            float v = Ss[bh * 1026 + t];
            float p = (v == -FLT_MAX) ? 0.f : __expf(v - mx[bb]);
            Ss[bh * 1026 + t] = p;
            sum[bb] += p;
        }
    }
    #pragma unroll
    for (int bb = 0; bb < 4; bb++)
        #pragma unroll
        for (int o = 16; o > 0; o >>= 1)
            sum[bb] += __shfl_xor_sync(0xffffffffu, sum[bb], o);

    #pragma unroll
    for (int bb = 0; bb < 4; bb++) {
        int bh = bh0 + bb;
        float inv = (sum[bb] > 0.f) ? (1.f / sum[bb]) : 0.f;
        float* srow = S + (size_t)bh * TT * TT + (size_t)q * TT;
        for (int i = 0; i < 32; i++) {
            int t = l + 32 * i;
            srow[t] = Ss[bh * 1026 + t] * inv;
        }
    }
}

// ---------------- 5) tf32 AV: O[b][q][h*64+d] --------------------------------
// Block 128q x 64d, warps 4m x 2n, warp tile 32x32, K-tile 32 over t.
__global__ void __launch_bounds__(256)
av_tf32(const float* __restrict__ P, const float* __restrict__ V, float* __restrict__ O)
{
    __shared__ unsigned Ps[128][36];
    __shared__ unsigned Vs[32][72];
    int tid = threadIdx.x, w = tid >> 5, l = tid & 31, g = l >> 2, t4 = l & 3;
    int q0 = blockIdx.x * 128;
    int bh = blockIdx.y, b_ = bh >> 2, h = bh & 3;
    int wm = (w >> 1) * 32, wn = (w & 1) * 32;

    float acc[2][4][4];
    #pragma unroll
    for (int i = 0; i < 2; i++)
        #pragma unroll
        for (int j = 0; j < 4; j++)
            #pragma unroll
            for (int e = 0; e < 4; e++) acc[i][j][e] = 0.f;

    const float* Pb = P + (size_t)bh * TT * TT;
    const float* Vb = V + (size_t)bh * TT * DKK;

    for (int t0 = 0; t0 < TT; t0 += 32) {
        int pr = tid >> 1, pk = (tid & 1) * 16;
        const float* pp = Pb + (size_t)(q0 + pr) * TT + t0 + pk;
        #pragma unroll
        for (int j = 0; j < 4; j++) {
            float4 v = *(const float4*)(pp + j * 4);
            Ps[pr][pk + j*4 + 0] = f2tf(v.x); Ps[pr][pk + j*4 + 1] = f2tf(v.y);
            Ps[pr][pk + j*4 + 2] = f2tf(v.z); Ps[pr][pk + j*4 + 3] = f2tf(v.w);
        }
        int vr = tid >> 3, vc = (tid & 7) * 8;
        const float* vp = Vb + (size_t)(t0 + vr) * DKK + vc;
        #pragma unroll
        for (int j = 0; j < 2; j++) {
            float4 v = *(const float4*)(vp + j * 4);
            Vs[vr][vc + j*4 + 0] = f2tf(v.x); Vs[vr][vc + j*4 + 1] = f2tf(v.y);
            Vs[vr][vc + j*4 + 2] = f2tf(v.z); Vs[vr][vc + j*4 + 3] = f2tf(v.w);
        }
        __syncthreads();
        #pragma unroll
        for (int ks = 0; ks < 4; ks++) {
            unsigned af[2][4], bf[4][2];
            #pragma unroll
            for (int mi = 0; mi < 2; mi++) {
                int r = wm + mi * 16;
                af[mi][0] = Ps[r + g    ][ks*8 + t4];
                af[mi][1] = Ps[r + g + 8][ks*8 + t4];
                af[mi][2] = Ps[r + g    ][ks*8 + t4 + 4];
                af[mi][3] = Ps[r + g + 8][ks*8 + t4 + 4];
            }
            #pragma unroll
            for (int ni = 0; ni < 4; ni++) {
                int c = wn + ni * 8 + g;
                bf[ni][0] = Vs[ks*8 + t4    ][c];
                bf[ni][1] = Vs[ks*8 + t4 + 4][c];
            }
            #pragma unroll
            for (int mi = 0; mi < 2; mi++)
                #pragma unroll
                for (int ni = 0; ni < 4; ni++)
                    mma8(acc[mi][ni], af[mi], bf[ni], acc[mi][ni]);
        }
        __syncthreads();
    }

    #pragma unroll
    for (int mi = 0; mi < 2; mi++)
        #pragma unroll
        for (int ni = 0; ni < 4; ni++) {
            int qq = q0 + wm + mi * 16 + g;
            int d  = wn + ni * 8 + 2 * t4;
            *(float2*)&O[((size_t)b_ * TT + qq) * FF + h * DKK + d] =
                make_float2(acc[mi][ni][0], acc[mi][ni][1]);
            *(float2*)&O[((size_t)b_ * TT + qq + 8) * FF + h * DKK + d] =
                make_float2(acc[mi][ni][2], acc[mi][ni][3]);
        }
}

// ---------------- launch ------------------------------------------------------
extern "C" void kernel_launch(void* const* d_in, const int* in_sizes, int n_in,
                              void* d_out, int out_size)
{
    (void)in_sizes; (void)n_in; (void)out_size;
    const float* x     = (const float*)d_in[0];
    const float* q_in  = (const float*)d_in[1];
    const float* pos_k = (const float*)d_in[2];
    const int*   mask  = (const int*)  d_in[3];
    const float* ln_g  = (const float*)d_in[4];
    const float* ln_b  = (const float*)d_in[5];
    const float* Wq    = (const float*)d_in[6];
    const float* bq    = (const float*)d_in[7];
    const float* Wk    = (const float*)d_in[8];
    const float* bk    = (const float*)d_in[9];
    const float* Wv    = (const float*)d_in[10];
    const float* bv    = (const float*)d_in[11];
    const float* Wo    = (const float*)d_in[12];
    const float* bo    = (const float*)d_in[13];
    float* out = (float*)d_out;

    float *p_xn, *p_q, *p_k, *p_v, *p_s, *p_att;
    cudaGetSymbolAddress((void**)&p_xn,  g_xn);
    cudaGetSymbolAddress((void**)&p_q,   g_q);
    cudaGetSymbolAddress((void**)&p_k,   g_k);
    cudaGetSymbolAddress((void**)&p_v,   g_v);
    cudaGetSymbolAddress((void**)&p_s,   g_s);
    cudaGetSymbolAddress((void**)&p_att, g_att);

    static const int QK_SMEM  = 2 * 128 * 68 * 4;                       // 69632
    static const int BSM_SMEM = (32 * 1026 + 32 * 68 + 128 * 68) * 4;   // 174848
    cudaFuncSetAttribute(qk_tf32,    cudaFuncAttributeMaxDynamicSharedMemorySize, QK_SMEM);
    cudaFuncSetAttribute(bsm_kernel, cudaFuncAttributeMaxDynamicSharedMemorySize, BSM_SMEM);

    ln_kernel<<<NROWS, 256>>>(x, ln_g, ln_b, p_xn);

    dim3 ggemm(FF / 128, NROWS / 128);
    gemm_tf32<<<ggemm, 256>>>(q_in, Wq, bq, p_q, 0);
    gemm_tf32<<<ggemm, 256>>>(p_xn, Wk, bk, p_k, 0);
    gemm_tf32<<<ggemm, 256>>>(p_xn, Wv, bv, p_v, 0);

    dim3 gqk(TT / 128, TT / 128, BHH);
    qk_tf32<<<gqk, 256, QK_SMEM>>>(p_q, p_k, p_s);

    bsm_kernel<<<TT, 256, BSM_SMEM>>>(p_q, pos_k, mask, p_s);

    dim3 gav(TT / 128, BHH);
    av_tf32<<<gav, 256>>>(p_s, p_v, p_att);

    gemm_tf32<<<ggemm, 256>>>(p_att, Wo, bo, out, 1);
}

// round 4
// speedup vs baseline: 1.6435x; 1.2448x over previous
#include <cuda_runtime.h>
#include <math.h>
#include <float.h>

#define BB    8
#define TT    1024
#define FF    256
#define NH    4
#define DKK   64
#define BHH   32
#define NROWS 8192

// ---------------- scratch ----------------------------------------------------
static __device__ float g_xn[NROWS * FF];
static __device__ float g_q [BHH * TT * DKK];
static __device__ float g_k [BHH * TT * DKK];
static __device__ float g_v [BHH * TT * DKK];
static __device__ float g_s [(size_t)BHH * TT * TT];
static __device__ float g_att[NROWS * FF];

// ---------------- helpers -----------------------------------------------------
__device__ __forceinline__ unsigned f2tf(float x) {
    unsigned r; asm("cvt.rna.tf32.f32 %0, %1;" : "=r"(r) : "f"(x)); return r;
}
__device__ __forceinline__ void mma8(float* d, const unsigned* a, const unsigned* b, const float* c) {
    asm volatile("mma.sync.aligned.m16n8k8.row.col.f32.tf32.tf32.f32 "
                 "{%0,%1,%2,%3}, {%4,%5,%6,%7}, {%8,%9}, {%10,%11,%12,%13};"
                 : "=f"(d[0]), "=f"(d[1]), "=f"(d[2]), "=f"(d[3])
                 : "r"(a[0]), "r"(a[1]), "r"(a[2]), "r"(a[3]),
                   "r"(b[0]), "r"(b[1]),
                   "f"(c[0]), "f"(c[1]), "f"(c[2]), "f"(c[3]));
}
__device__ __forceinline__ void cpa16(void* s, const void* g) {
    unsigned a = (unsigned)__cvta_generic_to_shared(s);
    asm volatile("cp.async.cg.shared.global [%0], [%1], 16;" :: "r"(a), "l"(g));
}
__device__ __forceinline__ void cp_commit() { asm volatile("cp.async.commit_group;"); }
template<int N> __device__ __forceinline__ void cp_wait() {
    asm volatile("cp.async.wait_group %0;" :: "n"(N));
}

// ---------------- 1) LayerNorm -----------------------------------------------
__global__ void ln_kernel(const float* __restrict__ x, const float* __restrict__ g,
                          const float* __restrict__ b, float* __restrict__ out)
{
    int row = blockIdx.x;
    int tid = threadIdx.x;
    float v = x[row * FF + tid];
    float s = v, sq = v * v;
    __shared__ float rs[8], rq[8];
    #pragma unroll
    for (int o = 16; o > 0; o >>= 1) {
        s  += __shfl_down_sync(0xffffffffu, s,  o);
        sq += __shfl_down_sync(0xffffffffu, sq, o);
    }
    if ((tid & 31) == 0) { rs[tid >> 5] = s; rq[tid >> 5] = sq; }
    __syncthreads();
    if (tid < 32) {
        float a = (tid < 8) ? rs[tid] : 0.f;
        float c = (tid < 8) ? rq[tid] : 0.f;
        #pragma unroll
        for (int o = 4; o > 0; o >>= 1) {
            a += __shfl_down_sync(0xffffffffu, a, o);
            c += __shfl_down_sync(0xffffffffu, c, o);
        }
        if (tid == 0) { rs[0] = a; rq[0] = c; }
    }
    __syncthreads();
    float mean = rs[0] * (1.f / FF);
    float var  = rq[0] * (1.f / FF) - mean * mean;
    float inv  = rsqrtf(fmaxf(var, 0.f) + 1e-5f);
    out[row * FF + tid] = (v - mean) * inv * g[tid] + b[tid];
}

// ---------------- 2) tf32 GEMM 128x64, BK=32, cp.async double buffered -------
// 8 warps: 4m x 2n, warp tile 32x32. MODE 0: scatter [bh][t][d]; 1: row-major.
template<int MODE>
__global__ void __launch_bounds__(256)
gemm_tf32(const float* __restrict__ A, const float* __restrict__ W,
          const float* __restrict__ bias, float* __restrict__ C)
{
    extern __shared__ float gsm[];
    float* As = gsm;                 // [2][128*36]
    float* Ws = gsm + 2 * 128 * 36;  // [2][32*72]
    int tid = threadIdx.x, w = tid >> 5, l = tid & 31, g = l >> 2, t4 = l & 3;
    int m0 = blockIdx.y * 128, n0 = blockIdx.x * 64;
    int wm = (w >> 1) * 32, wn = (w & 1) * 32;

    float acc[2][4][4];
    #pragma unroll
    for (int i = 0; i < 2; i++)
        #pragma unroll
        for (int j = 0; j < 4; j++)
            #pragma unroll
            for (int e = 0; e < 4; e++) acc[i][j][e] = 0.f;

    auto load_stage = [&](int buf, int k0) {
        float* Ab = As + buf * 128 * 36;
        #pragma unroll
        for (int j = 0; j < 4; j++) {
            int ch = tid + 256 * j;          // 1024 chunks, A tile 128x32
            int row = ch >> 3, c = ch & 7;
            cpa16(&Ab[row * 36 + c * 4], A + (size_t)(m0 + row) * FF + k0 + c * 4);
        }
        float* Wb = Ws + buf * 32 * 72;
        #pragma unroll
        for (int j = 0; j < 2; j++) {
            int ch = tid + 256 * j;          // 512 chunks, W tile 32x64
            int row = ch >> 4, c = ch & 15;
            cpa16(&Wb[row * 72 + c * 4], W + (size_t)(k0 + row) * FF + n0 + c * 4);
        }
    };

    load_stage(0, 0); cp_commit();

    for (int it = 0; it < 8; it++) {
        int buf = it & 1;
        cp_wait<0>();
        __syncthreads();
        if (it + 1 < 8) { load_stage(buf ^ 1, (it + 1) * 32); cp_commit(); }
        const float* Ab = As + buf * 128 * 36;
        const float* Wb = Ws + buf * 32 * 72;
        #pragma unroll
        for (int ks = 0; ks < 4; ks++) {
            unsigned af[2][4], bf[4][2];
            #pragma unroll
            for (int mi = 0; mi < 2; mi++) {
                int r = wm + mi * 16;
                af[mi][0] = f2tf(Ab[(r + g    ) * 36 + ks * 8 + t4]);
                af[mi][1] = f2tf(Ab[(r + g + 8) * 36 + ks * 8 + t4]);
                af[mi][2] = f2tf(Ab[(r + g    ) * 36 + ks * 8 + t4 + 4]);
                af[mi][3] = f2tf(Ab[(r + g + 8) * 36 + ks * 8 + t4 + 4]);
            }
            #pragma unroll
            for (int ni = 0; ni < 4; ni++) {
                int c = wn + ni * 8 + g;
                bf[ni][0] = f2tf(Wb[(ks * 8 + t4    ) * 72 + c]);
                bf[ni][1] = f2tf(Wb[(ks * 8 + t4 + 4) * 72 + c]);
            }
            #pragma unroll
            for (int mi = 0; mi < 2; mi++)
                #pragma unroll
                for (int ni = 0; ni < 4; ni++)
                    mma8(acc[mi][ni], af[mi], bf[ni], acc[mi][ni]);
        }
        __syncthreads();
    }

    #pragma unroll
    for (int mi = 0; mi < 2; mi++) {
        #pragma unroll
        for (int ni = 0; ni < 4; ni++) {
            int col = n0 + wn + ni * 8 + 2 * t4;
            float b0 = bias[col], b1 = bias[col + 1];
            int r0 = m0 + wm + mi * 16 + g;
            float2 o0 = make_float2(acc[mi][ni][0] + b0, acc[mi][ni][1] + b1);
            float2 o1 = make_float2(acc[mi][ni][2] + b0, acc[mi][ni][3] + b1);
            if (MODE == 0) {
                int h = col >> 6, d = col & 63;
                int b_ = r0 >> 10, t = r0 & 1023;
                *(float2*)&C[(((size_t)(b_*NH + h) * TT + t) * DKK) + d] = o0;
                int r1 = r0 + 8; b_ = r1 >> 10; t = r1 & 1023;
                *(float2*)&C[(((size_t)(b_*NH + h) * TT + t) * DKK) + d] = o1;
            } else {
                *(float2*)&C[(size_t)r0 * FF + col] = o0;
                *(float2*)&C[(size_t)(r0 + 8) * FF + col] = o1;
            }
        }
    }
}

// ---------------- 3) tf32 QK^T: 128q x 128t, K=64 ----------------------------
__global__ void __launch_bounds__(256)
qk_tf32(const float* __restrict__ Q, const float* __restrict__ K, float* __restrict__ S)
{
    extern __shared__ float qksm[];
    float* Qs = qksm;             // [128][68] raw fp32
    float* Ks = qksm + 128 * 68;  // [128][68]
    int tid = threadIdx.x, w = tid >> 5, l = tid & 31, g = l >> 2, t4 = l & 3;
    int bh = blockIdx.z, q0 = blockIdx.y * 128, t0 = blockIdx.x * 128;
    int wm = (w >> 2) * 64, wn = (w & 3) * 32;

    #pragma unroll
    for (int j = 0; j < 8; j++) {               // 2048 chunks Q, rows of 16 chunks
        int ch = tid + 256 * j;
        int row = ch >> 4, c = ch & 15;
        cpa16(&Qs[row * 68 + c * 4], Q + ((size_t)bh * TT + q0 + row) * DKK + c * 4);
    }
    #pragma unroll
    for (int j = 0; j < 8; j++) {
        int ch = tid + 256 * j;
        int row = ch >> 4, c = ch & 15;
        cpa16(&Ks[row * 68 + c * 4], K + ((size_t)bh * TT + t0 + row) * DKK + c * 4);
    }
    cp_commit(); cp_wait<0>();
    __syncthreads();

    float acc[4][4][4];
    #pragma unroll
    for (int i = 0; i < 4; i++)
        #pragma unroll
        for (int j = 0; j < 4; j++)
            #pragma unroll
            for (int e = 0; e < 4; e++) acc[i][j][e] = 0.f;

    #pragma unroll
    for (int ks = 0; ks < 8; ks++) {
        unsigned af[4][4], bf[4][2];
        #pragma unroll
        for (int mi = 0; mi < 4; mi++) {
            int r = wm + mi * 16;
            af[mi][0] = f2tf(Qs[(r + g    ) * 68 + ks * 8 + t4]);
            af[mi][1] = f2tf(Qs[(r + g + 8) * 68 + ks * 8 + t4]);
            af[mi][2] = f2tf(Qs[(r + g    ) * 68 + ks * 8 + t4 + 4]);
            af[mi][3] = f2tf(Qs[(r + g + 8) * 68 + ks * 8 + t4 + 4]);
        }
        #pragma unroll
        for (int ni = 0; ni < 4; ni++) {
            int c = wn + ni * 8 + g;
            bf[ni][0] = f2tf(Ks[c * 68 + ks * 8 + t4]);
            bf[ni][1] = f2tf(Ks[c * 68 + ks * 8 + t4 + 4]);
        }
        #pragma unroll
        for (int mi = 0; mi < 4; mi++)
            #pragma unroll
            for (int ni = 0; ni < 4; ni++)
                mma8(acc[mi][ni], af[mi], bf[ni], acc[mi][ni]);
    }

    float* dst = S + (size_t)bh * TT * TT;
    #pragma unroll
    for (int mi = 0; mi < 4; mi++)
        #pragma unroll
        for (int ni = 0; ni < 4; ni++) {
            int r0 = q0 + wm + mi * 16 + g;
            int col = t0 + wn + ni * 8 + 2 * t4;
            *(float2*)&dst[(size_t)r0 * TT + col] = make_float2(acc[mi][ni][0], acc[mi][ni][1]);
            *(float2*)&dst[(size_t)(r0 + 8) * TT + col] = make_float2(acc[mi][ni][2], acc[mi][ni][3]);
        }
}

// ---------------- 4) fused bias + mask + softmax (pipelined pos_k) -----------
// CTA per q. Bias GEMM [32bh x 64d] @ [64d x 1024t] in 16 chunks of 64t,
// cp.async double buffered; then per-warp softmax on 4 bh rows.
__global__ void __launch_bounds__(256)
bsm_kernel(const float* __restrict__ Qg, const float* __restrict__ PK,
           const int* __restrict__ mask, float* __restrict__ S)
{
    extern __shared__ float sm[];
    float* Ss = sm;                        // [32][1026]
    float* Qs = sm + 32 * 1026;            // [32][68] raw fp32
    float* Ps = Qs + 32 * 68;              // [2][64][68] raw fp32
    int tid = threadIdx.x, w = tid >> 5, l = tid & 31, g = l >> 2, t4 = l & 3;
    int q = blockIdx.x;

    {
        int bh = tid >> 3, dg = (tid & 7) * 8;
        const float* src = Qg + ((size_t)bh * TT + q) * DKK + dg;
        *(float4*)&Qs[bh * 68 + dg]     = *(const float4*)(src);
        *(float4*)&Qs[bh * 68 + dg + 4] = *(const float4*)(src + 4);
    }

    auto load_chunk = [&](int buf, int c) {
        float* Pb = Ps + buf * 64 * 68;
        int t0 = c * 64;
        #pragma unroll
        for (int j = 0; j < 4; j++) {        // 64 rows x 16 chunks = 1024
            int ch = tid + 256 * j;
            int row = ch >> 4, cc = ch & 15;
            cpa16(&Pb[row * 68 + cc * 4], PK + ((size_t)q * TT + t0 + row) * DKK + cc * 4);
        }
    };

    load_chunk(0, 0); cp_commit();
    __syncthreads();    // Qs visible

    for (int c = 0; c < 16; c++) {
        int buf = c & 1;
        cp_wait<0>();
        __syncthreads();
        if (c + 1 < 16) { load_chunk(buf ^ 1, c + 1); cp_commit(); }
        const float* Pb = Ps + buf * 64 * 68;

        float acc[2][4];
        #pragma unroll
        for (int mi = 0; mi < 2; mi++)
            #pragma unroll
            for (int e = 0; e < 4; e++) acc[mi][e] = 0.f;

        #pragma unroll
        for (int ks = 0; ks < 8; ks++) {
            unsigned af[2][4], bf[2];
            #pragma unroll
            for (int mi = 0; mi < 2; mi++) {
                int r = mi * 16;
                af[mi][0] = f2tf(Qs[(r + g    ) * 68 + ks * 8 + t4]);
                af[mi][1] = f2tf(Qs[(r + g + 8) * 68 + ks * 8 + t4]);
                af[mi][2] = f2tf(Qs[(r + g    ) * 68 + ks * 8 + t4 + 4]);
                af[mi][3] = f2tf(Qs[(r + g + 8) * 68 + ks * 8 + t4 + 4]);
            }
            int cn = w * 8 + g;
            bf[0] = f2tf(Pb[cn * 68 + ks * 8 + t4]);
            bf[1] = f2tf(Pb[cn * 68 + ks * 8 + t4 + 4]);
            #pragma unroll
            for (int mi = 0; mi < 2; mi++)
                mma8(acc[mi], af[mi], bf, acc[mi]);
        }
        #pragma unroll
        for (int mi = 0; mi < 2; mi++) {
            int row = mi * 16 + g;
            int col = c * 64 + w * 8 + 2 * t4;
            Ss[row * 1026 + col]     = acc[mi][0];
            Ss[row * 1026 + col + 1] = acc[mi][1];
            Ss[(row + 8) * 1026 + col]     = acc[mi][2];
            Ss[(row + 8) * 1026 + col + 1] = acc[mi][3];
        }
        __syncthreads();
    }

    // ---- combine + mask + softmax: warp w owns bh = 4w..4w+3 (b = w) ----
    int bh0 = w * 4;
    const int* mrow = mask + ((size_t)w * TT + q) * TT;
    float mx[4] = {-FLT_MAX, -FLT_MAX, -FLT_MAX, -FLT_MAX};
    #pragma unroll
    for (int bb = 0; bb < 4; bb++) {
        int bh = bh0 + bb;
        const float* srow = S + (size_t)bh * TT * TT + (size_t)q * TT;
        for (int i = 0; i < 32; i++) {
            int t = l + 32 * i;
            float v = (mrow[t] == 0) ? -FLT_MAX
                                     : (srow[t] + Ss[bh * 1026 + t]) * 0.125f;
            Ss[bh * 1026 + t] = v;
            mx[bb] = fmaxf(mx[bb], v);
        }
    }
    #pragma unroll
    for (int bb = 0; bb < 4; bb++)
        #pragma unroll
        for (int o = 16; o > 0; o >>= 1)
            mx[bb] = fmaxf(mx[bb], __shfl_xor_sync(0xffffffffu, mx[bb], o));

    float sum[4] = {0.f, 0.f, 0.f, 0.f};
    #pragma unroll
    for (int bb = 0; bb < 4; bb++) {
        int bh = bh0 + bb;
        for (int i = 0; i < 32; i++) {
            int t = l + 32 * i;
            float v = Ss[bh * 1026 + t];
            float p = (v == -FLT_MAX) ? 0.f : __expf(v - mx[bb]);
            Ss[bh * 1026 + t] = p;
            sum[bb] += p;
        }
    }
    #pragma unroll
    for (int bb = 0; bb < 4; bb++)
        #pragma unroll
        for (int o = 16; o > 0; o >>= 1)
            sum[bb] += __shfl_xor_sync(0xffffffffu, sum[bb], o);

    #pragma unroll
    for (int bb = 0; bb < 4; bb++) {
        int bh = bh0 + bb;
        float inv = (sum[bb] > 0.f) ? (1.f / sum[bb]) : 0.f;
        float* srow = S + (size_t)bh * TT * TT + (size_t)q * TT;
        for (int i = 0; i < 32; i++) {
            int t = l + 32 * i;
            srow[t] = Ss[bh * 1026 + t] * inv;
        }
    }
}

// ---------------- 5) tf32 AV: 128q x 64d, BK=64, double buffered -------------
// 8 warps: 4m x 2n, warp tile 32x32.
__global__ void __launch_bounds__(256)
av_tf32(const float* __restrict__ P, const float* __restrict__ V, float* __restrict__ O)
{
    extern __shared__ float avsm[];
    float* Ps = avsm;                  // [2][128][68]
    float* Vs = avsm + 2 * 128 * 68;   // [2][64][72]
    int tid = threadIdx.x, w = tid >> 5, l = tid & 31, g = l >> 2, t4 = l & 3;
    int q0 = blockIdx.x * 128;
    int bh = blockIdx.y, b_ = bh >> 2, h = bh & 3;
    int wm = (w >> 1) * 32, wn = (w & 1) * 32;

    float acc[2][4][4];
    #pragma unroll
    for (int i = 0; i < 2; i++)
        #pragma unroll
        for (int j = 0; j < 4; j++)
            #pragma unroll
            for (int e = 0; e < 4; e++) acc[i][j][e] = 0.f;

    const float* Pb_g = P + (size_t)bh * TT * TT;
    const float* Vb_g = V + (size_t)bh * TT * DKK;

    auto load_stage = [&](int buf, int t0) {
        float* Pd = Ps + buf * 128 * 68;
        #pragma unroll
        for (int j = 0; j < 8; j++) {           // P tile 128 x 64 = 2048 chunks
            int ch = tid + 256 * j;
            int row = ch >> 4, c = ch & 15;
            cpa16(&Pd[row * 68 + c * 4], Pb_g + (size_t)(q0 + row) * TT + t0 + c * 4);
        }
        float* Vd = Vs + buf * 64 * 72;
        #pragma unroll
        for (int j = 0; j < 4; j++) {           // V tile 64 x 64 = 1024 chunks
            int ch = tid + 256 * j;
            int row = ch >> 4, c = ch & 15;
            cpa16(&Vd[row * 72 + c * 4], Vb_g + (size_t)(t0 + row) * DKK + c * 4);
        }
    };

    load_stage(0, 0); cp_commit();

    for (int it = 0; it < 16; it++) {
        int buf = it & 1;
        cp_wait<0>();
        __syncthreads();
        if (it + 1 < 16) { load_stage(buf ^ 1, (it + 1) * 64); cp_commit(); }
        const float* Pd = Ps + buf * 128 * 68;
        const float* Vd = Vs + buf * 64 * 72;
        #pragma unroll
        for (int ks = 0; ks < 8; ks++) {
            unsigned af[2][4], bf[4][2];
            #pragma unroll
            for (int mi = 0; mi < 2; mi++) {
                int r = wm + mi * 16;
                af[mi][0] = f2tf(Pd[(r + g    ) * 68 + ks * 8 + t4]);
                af[mi][1] = f2tf(Pd[(r + g + 8) * 68 + ks * 8 + t4]);
                af[mi][2] = f2tf(Pd[(r + g    ) * 68 + ks * 8 + t4 + 4]);
                af[mi][3] = f2tf(Pd[(r + g + 8) * 68 + ks * 8 + t4 + 4]);
            }
            #pragma unroll
            for (int ni = 0; ni < 4; ni++) {
                int c = wn + ni * 8 + g;
                bf[ni][0] = f2tf(Vd[(ks * 8 + t4    ) * 72 + c]);
                bf[ni][1] = f2tf(Vd[(ks * 8 + t4 + 4) * 72 + c]);
            }
            #pragma unroll
            for (int mi = 0; mi < 2; mi++)
                #pragma unroll
                for (int ni = 0; ni < 4; ni++)
                    mma8(acc[mi][ni], af[mi], bf[ni], acc[mi][ni]);
        }
        __syncthreads();
    }

    #pragma unroll
    for (int mi = 0; mi < 2; mi++)
        #pragma unroll
        for (int ni = 0; ni < 4; ni++) {
            int qq = q0 + wm + mi * 16 + g;
            int d  = wn + ni * 8 + 2 * t4;
            *(float2*)&O[((size_t)b_ * TT + qq) * FF + h * DKK + d] =
                make_float2(acc[mi][ni][0], acc[mi][ni][1]);
            *(float2*)&O[((size_t)b_ * TT + qq + 8) * FF + h * DKK + d] =
                make_float2(acc[mi][ni][2], acc[mi][ni][3]);
        }
}

// ---------------- launch ------------------------------------------------------
extern "C" void kernel_launch(void* const* d_in, const int* in_sizes, int n_in,
                              void* d_out, int out_size)
{
    (void)in_sizes; (void)n_in; (void)out_size;
    const float* x     = (const float*)d_in[0];
    const float* q_in  = (const float*)d_in[1];
    const float* pos_k = (const float*)d_in[2];
    const int*   mask  = (const int*)  d_in[3];
    const float* ln_g  = (const float*)d_in[4];
    const float* ln_b  = (const float*)d_in[5];
    const float* Wq    = (const float*)d_in[6];
    const float* bq    = (const float*)d_in[7];
    const float* Wk    = (const float*)d_in[8];
    const float* bk    = (const float*)d_in[9];
    const float* Wv    = (const float*)d_in[10];
    const float* bv    = (const float*)d_in[11];
    const float* Wo    = (const float*)d_in[12];
    const float* bo    = (const float*)d_in[13];
    float* out = (float*)d_out;

    float *p_xn, *p_q, *p_k, *p_v, *p_s, *p_att;
    cudaGetSymbolAddress((void**)&p_xn,  g_xn);
    cudaGetSymbolAddress((void**)&p_q,   g_q);
    cudaGetSymbolAddress((void**)&p_k,   g_k);
    cudaGetSymbolAddress((void**)&p_v,   g_v);
    cudaGetSymbolAddress((void**)&p_s,   g_s);
    cudaGetSymbolAddress((void**)&p_att, g_att);

    static const int GEMM_SMEM = (2 * 128 * 36 + 2 * 32 * 72) * 4;       // 55296
    static const int QK_SMEM   = 2 * 128 * 68 * 4;                       // 69632
    static const int BSM_SMEM  = (32 * 1026 + 32 * 68 + 2 * 64 * 68) * 4; // 174848
    static const int AV_SMEM   = (2 * 128 * 68 + 2 * 64 * 72) * 4;       // 106496
    cudaFuncSetAttribute(gemm_tf32<0>, cudaFuncAttributeMaxDynamicSharedMemorySize, GEMM_SMEM);
    cudaFuncSetAttribute(gemm_tf32<1>, cudaFuncAttributeMaxDynamicSharedMemorySize, GEMM_SMEM);
    cudaFuncSetAttribute(qk_tf32,      cudaFuncAttributeMaxDynamicSharedMemorySize, QK_SMEM);
    cudaFuncSetAttribute(bsm_kernel,   cudaFuncAttributeMaxDynamicSharedMemorySize, BSM_SMEM);
    cudaFuncSetAttribute(av_tf32,      cudaFuncAttributeMaxDynamicSharedMemorySize, AV_SMEM);

    ln_kernel<<<NROWS, 256>>>(x, ln_g, ln_b, p_xn);

    dim3 ggemm(FF / 64, NROWS / 128);   // (4, 64) = 256 CTAs
    gemm_tf32<0><<<ggemm, 256, GEMM_SMEM>>>(q_in, Wq, bq, p_q);
    gemm_tf32<0><<<ggemm, 256, GEMM_SMEM>>>(p_xn, Wk, bk, p_k);
    gemm_tf32<0><<<ggemm, 256, GEMM_SMEM>>>(p_xn, Wv, bv, p_v);

    dim3 gqk(TT / 128, TT / 128, BHH);
    qk_tf32<<<gqk, 256, QK_SMEM>>>(p_q, p_k, p_s);

    bsm_kernel<<<TT, 256, BSM_SMEM>>>(p_q, pos_k, mask, p_s);

    dim3 gav(TT / 128, BHH);
    av_tf32<<<gav, 256, AV_SMEM>>>(p_s, p_v, p_att);

    gemm_tf32<1><<<ggemm, 256, GEMM_SMEM>>>(p_att, Wo, bo, out);
}

// round 5
// speedup vs baseline: 1.8640x; 1.1342x over previous
#include <cuda_runtime.h>
#include <math.h>
#include <float.h>

#define BB    8
#define TT    1024
#define FF    256
#define NH    4
#define DKK   64
#define BHH   32
#define NROWS 8192

// ---------------- scratch ----------------------------------------------------
static __device__ float g_xn[NROWS * FF];
static __device__ float g_q [BHH * TT * DKK];
static __device__ float g_k [BHH * TT * DKK];
static __device__ float g_v [BHH * TT * DKK];
static __device__ float g_s [(size_t)BHH * TT * TT];
static __device__ float g_att[NROWS * FF];

// ---------------- helpers -----------------------------------------------------
__device__ __forceinline__ unsigned f2tf(float x) {
    unsigned r; asm("cvt.rna.tf32.f32 %0, %1;" : "=r"(r) : "f"(x)); return r;
}
__device__ __forceinline__ void mma8(float* d, const unsigned* a, const unsigned* b, const float* c) {
    asm volatile("mma.sync.aligned.m16n8k8.row.col.f32.tf32.tf32.f32 "
                 "{%0,%1,%2,%3}, {%4,%5,%6,%7}, {%8,%9}, {%10,%11,%12,%13};"
                 : "=f"(d[0]), "=f"(d[1]), "=f"(d[2]), "=f"(d[3])
                 : "r"(a[0]), "r"(a[1]), "r"(a[2]), "r"(a[3]),
                   "r"(b[0]), "r"(b[1]),
                   "f"(c[0]), "f"(c[1]), "f"(c[2]), "f"(c[3]));
}
__device__ __forceinline__ void cpa16(void* s, const void* g) {
    unsigned a = (unsigned)__cvta_generic_to_shared(s);
    asm volatile("cp.async.cg.shared.global [%0], [%1], 16;" :: "r"(a), "l"(g));
}
__device__ __forceinline__ void cp_commit() { asm volatile("cp.async.commit_group;"); }
template<int N> __device__ __forceinline__ void cp_wait() {
    asm volatile("cp.async.wait_group %0;" :: "n"(N));
}

// ---------------- 1) LayerNorm -----------------------------------------------
__global__ void ln_kernel(const float* __restrict__ x, const float* __restrict__ g,
                          const float* __restrict__ b, float* __restrict__ out)
{
    int row = blockIdx.x;
    int tid = threadIdx.x;
    float v = x[row * FF + tid];
    float s = v, sq = v * v;
    __shared__ float rs[8], rq[8];
    #pragma unroll
    for (int o = 16; o > 0; o >>= 1) {
        s  += __shfl_down_sync(0xffffffffu, s,  o);
        sq += __shfl_down_sync(0xffffffffu, sq, o);
    }
    if ((tid & 31) == 0) { rs[tid >> 5] = s; rq[tid >> 5] = sq; }
    __syncthreads();
    if (tid < 32) {
        float a = (tid < 8) ? rs[tid] : 0.f;
        float c = (tid < 8) ? rq[tid] : 0.f;
        #pragma unroll
        for (int o = 4; o > 0; o >>= 1) {
            a += __shfl_down_sync(0xffffffffu, a, o);
            c += __shfl_down_sync(0xffffffffu, c, o);
        }
        if (tid == 0) { rs[0] = a; rq[0] = c; }
    }
    __syncthreads();
    float mean = rs[0] * (1.f / FF);
    float var  = rq[0] * (1.f / FF) - mean * mean;
    float inv  = rsqrtf(fmaxf(var, 0.f) + 1e-5f);
    out[row * FF + tid] = (v - mean) * inv * g[tid] + b[tid];
}

// ---------------- 2) tf32 GEMM core: 128x64, BK=32, 3-stage cp.async ---------
// 8 warps: 4m x 2n, warp tile 32x32. MODE 0: scatter [bh][t][d]; 1: row-major.
#define G_STAGE_F (128 * 36 + 32 * 72)   // floats per stage: A then W

__device__ __forceinline__ void gemm_body(
    const float* __restrict__ A, const float* __restrict__ W,
    const float* __restrict__ bias, float* __restrict__ C, int MODE)
{
    extern __shared__ float gsm[];
    int tid = threadIdx.x, w = tid >> 5, l = tid & 31, g = l >> 2, t4 = l & 3;
    int m0 = blockIdx.y * 128, n0 = blockIdx.x * 64;
    int wm = (w >> 1) * 32, wn = (w & 1) * 32;

    float acc[2][4][4];
    #pragma unroll
    for (int i = 0; i < 2; i++)
        #pragma unroll
        for (int j = 0; j < 4; j++)
            #pragma unroll
            for (int e = 0; e < 4; e++) acc[i][j][e] = 0.f;

    auto load_stage = [&](int s, int k0) {
        float* Ab = gsm + s * G_STAGE_F;
        float* Wb = Ab + 128 * 36;
        #pragma unroll
        for (int j = 0; j < 4; j++) {
            int ch = tid + 256 * j;          // A tile 128x32 = 1024 x 16B
            int row = ch >> 3, c = ch & 7;
            cpa16(&Ab[row * 36 + c * 4], A + (size_t)(m0 + row) * FF + k0 + c * 4);
        }
        #pragma unroll
        for (int j = 0; j < 2; j++) {
            int ch = tid + 256 * j;          // W tile 32x64 = 512 x 16B
            int row = ch >> 4, c = ch & 15;
            cpa16(&Wb[row * 72 + c * 4], W + (size_t)(k0 + row) * FF + n0 + c * 4);
        }
        cp_commit();
    };

    load_stage(0, 0);
    load_stage(1, 32);

    for (int it = 0; it < 8; it++) {
        int s = it % 3;
        if (it == 7) cp_wait<0>(); else cp_wait<1>();
        __syncthreads();
        if (it + 2 < 8) load_stage((it + 2) % 3, (it + 2) * 32);
        const float* Ab = gsm + s * G_STAGE_F;
        const float* Wb = Ab + 128 * 36;
        #pragma unroll
        for (int ks = 0; ks < 4; ks++) {
            unsigned af[2][4], bf[4][2];
            #pragma unroll
            for (int mi = 0; mi < 2; mi++) {
                int r = wm + mi * 16;
                af[mi][0] = f2tf(Ab[(r + g    ) * 36 + ks * 8 + t4]);
                af[mi][1] = f2tf(Ab[(r + g + 8) * 36 + ks * 8 + t4]);
                af[mi][2] = f2tf(Ab[(r + g    ) * 36 + ks * 8 + t4 + 4]);
                af[mi][3] = f2tf(Ab[(r + g + 8) * 36 + ks * 8 + t4 + 4]);
            }
            #pragma unroll
            for (int ni = 0; ni < 4; ni++) {
                int c = wn + ni * 8 + g;
                bf[ni][0] = f2tf(Wb[(ks * 8 + t4    ) * 72 + c]);
                bf[ni][1] = f2tf(Wb[(ks * 8 + t4 + 4) * 72 + c]);
            }
            #pragma unroll
            for (int mi = 0; mi < 2; mi++)
                #pragma unroll
                for (int ni = 0; ni < 4; ni++)
                    mma8(acc[mi][ni], af[mi], bf[ni], acc[mi][ni]);
        }
        __syncthreads();
    }

    #pragma unroll
    for (int mi = 0; mi < 2; mi++) {
        #pragma unroll
        for (int ni = 0; ni < 4; ni++) {
            int col = n0 + wn + ni * 8 + 2 * t4;
            float b0 = bias[col], b1 = bias[col + 1];
            int r0 = m0 + wm + mi * 16 + g;
            float2 o0 = make_float2(acc[mi][ni][0] + b0, acc[mi][ni][1] + b1);
            float2 o1 = make_float2(acc[mi][ni][2] + b0, acc[mi][ni][3] + b1);
            if (MODE == 0) {
                int h = col >> 6, d = col & 63;
                int b_ = r0 >> 10, t = r0 & 1023;
                *(float2*)&C[(((size_t)(b_*NH + h) * TT + t) * DKK) + d] = o0;
                int r1 = r0 + 8; b_ = r1 >> 10; t = r1 & 1023;
                *(float2*)&C[(((size_t)(b_*NH + h) * TT + t) * DKK) + d] = o1;
            } else {
                *(float2*)&C[(size_t)r0 * FF + col] = o0;
                *(float2*)&C[(size_t)(r0 + 8) * FF + col] = o1;
            }
        }
    }
}

// merged Q/K/V projections: blockIdx.z selects which
__global__ void __launch_bounds__(256)
proj3_kernel(const float* __restrict__ Aq, const float* __restrict__ Axn,
             const float* __restrict__ Wq, const float* __restrict__ bq,
             const float* __restrict__ Wk, const float* __restrict__ bk,
             const float* __restrict__ Wv, const float* __restrict__ bv,
             float* __restrict__ Cq, float* __restrict__ Ck, float* __restrict__ Cv)
{
    int z = blockIdx.z;
    const float* A = (z == 0) ? Aq : Axn;
    const float* W = (z == 0) ? Wq : (z == 1) ? Wk : Wv;
    const float* b = (z == 0) ? bq : (z == 1) ? bk : bv;
    float* C       = (z == 0) ? Cq : (z == 1) ? Ck : Cv;
    gemm_body(A, W, b, C, 0);
}

__global__ void __launch_bounds__(256)
gemm_out_kernel(const float* __restrict__ A, const float* __restrict__ W,
                const float* __restrict__ bias, float* __restrict__ C)
{
    gemm_body(A, W, bias, C, 1);
}

// ---------------- 3) tf32 QK^T: 128q x 128t, K=64 ----------------------------
__global__ void __launch_bounds__(256)
qk_tf32(const float* __restrict__ Q, const float* __restrict__ K, float* __restrict__ S)
{
    extern __shared__ float qksm[];
    float* Qs = qksm;             // [128][68]
    float* Ks = qksm + 128 * 68;  // [128][68]
    int tid = threadIdx.x, w = tid >> 5, l = tid & 31, g = l >> 2, t4 = l & 3;
    int bh = blockIdx.z, q0 = blockIdx.y * 128, t0 = blockIdx.x * 128;
    int wm = (w >> 2) * 64, wn = (w & 3) * 32;

    #pragma unroll
    for (int j = 0; j < 8; j++) {
        int ch = tid + 256 * j;
        int row = ch >> 4, c = ch & 15;
        cpa16(&Qs[row * 68 + c * 4], Q + ((size_t)bh * TT + q0 + row) * DKK + c * 4);
    }
    #pragma unroll
    for (int j = 0; j < 8; j++) {
        int ch = tid + 256 * j;
        int row = ch >> 4, c = ch & 15;
        cpa16(&Ks[row * 68 + c * 4], K + ((size_t)bh * TT + t0 + row) * DKK + c * 4);
    }
    cp_commit(); cp_wait<0>();
    __syncthreads();

    float acc[4][4][4];
    #pragma unroll
    for (int i = 0; i < 4; i++)
        #pragma unroll
        for (int j = 0; j < 4; j++)
            #pragma unroll
            for (int e = 0; e < 4; e++) acc[i][j][e] = 0.f;

    #pragma unroll
    for (int ks = 0; ks < 8; ks++) {
        unsigned af[4][4], bf[4][2];
        #pragma unroll
        for (int mi = 0; mi < 4; mi++) {
            int r = wm + mi * 16;
            af[mi][0] = f2tf(Qs[(r + g    ) * 68 + ks * 8 + t4]);
            af[mi][1] = f2tf(Qs[(r + g + 8) * 68 + ks * 8 + t4]);
            af[mi][2] = f2tf(Qs[(r + g    ) * 68 + ks * 8 + t4 + 4]);
            af[mi][3] = f2tf(Qs[(r + g + 8) * 68 + ks * 8 + t4 + 4]);
        }
        #pragma unroll
        for (int ni = 0; ni < 4; ni++) {
            int c = wn + ni * 8 + g;
            bf[ni][0] = f2tf(Ks[c * 68 + ks * 8 + t4]);
            bf[ni][1] = f2tf(Ks[c * 68 + ks * 8 + t4 + 4]);
        }
        #pragma unroll
        for (int mi = 0; mi < 4; mi++)
            #pragma unroll
            for (int ni = 0; ni < 4; ni++)
                mma8(acc[mi][ni], af[mi], bf[ni], acc[mi][ni]);
    }

    float* dst = S + (size_t)bh * TT * TT;
    #pragma unroll
    for (int mi = 0; mi < 4; mi++)
        #pragma unroll
        for (int ni = 0; ni < 4; ni++) {
            int r0 = q0 + wm + mi * 16 + g;
            int col = t0 + wn + ni * 8 + 2 * t4;
            *(float2*)&dst[(size_t)r0 * TT + col] = make_float2(acc[mi][ni][0], acc[mi][ni][1]);
            *(float2*)&dst[(size_t)(r0 + 8) * TT + col] = make_float2(acc[mi][ni][2], acc[mi][ni][3]);
        }
}

// ---------------- 4) fused bias + mask + softmax, 512 threads ----------------
// CTA per q. Bias GEMM [32bh x 64d] @ [64d x 1024t], 8 chunks of 128t,
// cp.async double-buffered; softmax: 16 warps x 2 bh rows, float4 passes.
__global__ void __launch_bounds__(512)
bsm_kernel(const float* __restrict__ Qg, const float* __restrict__ PK,
           const int* __restrict__ mask, float* __restrict__ S)
{
    extern __shared__ float sm[];
    float* Ss = sm;                        // [32][1026]
    float* Qs = sm + 32 * 1026;            // [32][68]
    float* Ps = Qs + 32 * 68;              // [2][128][68]
    int tid = threadIdx.x, w = tid >> 5, l = tid & 31, g = l >> 2, t4 = l & 3;
    int q = blockIdx.x;

    if (tid < 256) {
        int bh = tid >> 3, dg = (tid & 7) * 8;
        const float* src = Qg + ((size_t)bh * TT + q) * DKK + dg;
        *(float4*)&Qs[bh * 68 + dg]     = *(const float4*)(src);
        *(float4*)&Qs[bh * 68 + dg + 4] = *(const float4*)(src + 4);
    }

    auto load_chunk = [&](int buf, int c) {
        float* Pb = Ps + buf * 128 * 68;
        int t0 = c * 128;
        #pragma unroll
        for (int j = 0; j < 4; j++) {        // 128 rows x 16 = 2048 chunks / 512 thr
            int ch = tid + 512 * j;
            int row = ch >> 4, cc = ch & 15;
            cpa16(&Pb[row * 68 + cc * 4], PK + ((size_t)q * TT + t0 + row) * DKK + cc * 4);
        }
        cp_commit();
    };

    load_chunk(0, 0);
    __syncthreads();    // Qs visible

    for (int c = 0; c < 8; c++) {
        int buf = c & 1;
        cp_wait<0>();
        __syncthreads();
        if (c + 1 < 8) load_chunk(buf ^ 1, c + 1);
        const float* Pb = Ps + buf * 128 * 68;

        float acc[2][4];
        #pragma unroll
        for (int mi = 0; mi < 2; mi++)
            #pragma unroll
            for (int e = 0; e < 4; e++) acc[mi][e] = 0.f;

        #pragma unroll
        for (int ks = 0; ks < 8; ks++) {
            unsigned af[2][4], bf[2];
            #pragma unroll
            for (int mi = 0; mi < 2; mi++) {
                int r = mi * 16;
                af[mi][0] = f2tf(Qs[(r + g    ) * 68 + ks * 8 + t4]);
                af[mi][1] = f2tf(Qs[(r + g + 8) * 68 + ks * 8 + t4]);
                af[mi][2] = f2tf(Qs[(r + g    ) * 68 + ks * 8 + t4 + 4]);
                af[mi][3] = f2tf(Qs[(r + g + 8) * 68 + ks * 8 + t4 + 4]);
            }
            int cn = w * 8 + g;
            bf[0] = f2tf(Pb[cn * 68 + ks * 8 + t4]);
            bf[1] = f2tf(Pb[cn * 68 + ks * 8 + t4 + 4]);
            #pragma unroll
            for (int mi = 0; mi < 2; mi++)
                mma8(acc[mi], af[mi], bf, acc[mi]);
        }
        #pragma unroll
        for (int mi = 0; mi < 2; mi++) {
            int row = mi * 16 + g;
            int col = c * 128 + w * 8 + 2 * t4;
            Ss[row * 1026 + col]     = acc[mi][0];
            Ss[row * 1026 + col + 1] = acc[mi][1];
            Ss[(row + 8) * 1026 + col]     = acc[mi][2];
            Ss[(row + 8) * 1026 + col + 1] = acc[mi][3];
        }
        __syncthreads();
    }

    // ---- combine + mask + softmax: warp w owns bh = 2w, 2w+1 ----
    #pragma unroll
    for (int bb = 0; bb < 2; bb++) {
        int bh = w * 2 + bb;
        int b_ = bh >> 2;
        const int* mrow  = mask + ((size_t)b_ * TT + q) * TT;
        float* srow = S + (size_t)bh * TT * TT + (size_t)q * TT;
        float* ssr  = Ss + bh * 1026;

        float mx = -FLT_MAX;
        #pragma unroll
        for (int i = 0; i < 8; i++) {
            int t = 4 * (l + 32 * i);
            float4 sv = *(const float4*)&srow[t];
            int4   mv = *(const int4*)&mrow[t];
            float4 bv = make_float4(ssr[t], ssr[t+1], ssr[t+2], ssr[t+3]);
            float4 o;
            o.x = (mv.x == 0) ? -FLT_MAX : (sv.x + bv.x) * 0.125f;
            o.y = (mv.y == 0) ? -FLT_MAX : (sv.y + bv.y) * 0.125f;
            o.z = (mv.z == 0) ? -FLT_MAX : (sv.z + bv.z) * 0.125f;
            o.w = (mv.w == 0) ? -FLT_MAX : (sv.w + bv.w) * 0.125f;
            ssr[t] = o.x; ssr[t+1] = o.y; ssr[t+2] = o.z; ssr[t+3] = o.w;
            mx = fmaxf(mx, fmaxf(fmaxf(o.x, o.y), fmaxf(o.z, o.w)));
        }
        #pragma unroll
        for (int o = 16; o > 0; o >>= 1)
            mx = fmaxf(mx, __shfl_xor_sync(0xffffffffu, mx, o));

        float sum = 0.f;
        #pragma unroll
        for (int i = 0; i < 8; i++) {
            int t = 4 * (l + 32 * i);
            #pragma unroll
            for (int j = 0; j < 4; j++) {
                float v = ssr[t + j];
                float p = (v == -FLT_MAX) ? 0.f : __expf(v - mx);
                ssr[t + j] = p;
                sum += p;
            }
        }
        #pragma unroll
        for (int o = 16; o > 0; o >>= 1)
            sum += __shfl_xor_sync(0xffffffffu, sum, o);
        float inv = (sum > 0.f) ? (1.f / sum) : 0.f;

        #pragma unroll
        for (int i = 0; i < 8; i++) {
            int t = 4 * (l + 32 * i);
            float4 o;
            o.x = ssr[t] * inv; o.y = ssr[t+1] * inv;
            o.z = ssr[t+2] * inv; o.w = ssr[t+3] * inv;
            *(float4*)&srow[t] = o;
        }
    }
}

// ---------------- 5) tf32 AV: 128q x 64d, BK=64, double buffered -------------
__global__ void __launch_bounds__(256)
av_tf32(const float* __restrict__ P, const float* __restrict__ V, float* __restrict__ O)
{
    extern __shared__ float avsm[];
    float* Ps = avsm;                  // [2][128][68]
    float* Vs = avsm + 2 * 128 * 68;   // [2][64][72]
    int tid = threadIdx.x, w = tid >> 5, l = tid & 31, g = l >> 2, t4 = l & 3;
    int q0 = blockIdx.x * 128;
    int bh = blockIdx.y, b_ = bh >> 2, h = bh & 3;
    int wm = (w >> 1) * 32, wn = (w & 1) * 32;

    float acc[2][4][4];
    #pragma unroll
    for (int i = 0; i < 2; i++)
        #pragma unroll
        for (int j = 0; j < 4; j++)
            #pragma unroll
            for (int e = 0; e < 4; e++) acc[i][j][e] = 0.f;

    const float* Pb_g = P + (size_t)bh * TT * TT;
    const float* Vb_g = V + (size_t)bh * TT * DKK;

    auto load_stage = [&](int buf, int t0) {
        float* Pd = Ps + buf * 128 * 68;
        #pragma unroll
        for (int j = 0; j < 8; j++) {
            int ch = tid + 256 * j;
            int row = ch >> 4, c = ch & 15;
            cpa16(&Pd[row * 68 + c * 4], Pb_g + (size_t)(q0 + row) * TT + t0 + c * 4);
        }
        float* Vd = Vs + buf * 64 * 72;
        #pragma unroll
        for (int j = 0; j < 4; j++) {
            int ch = tid + 256 * j;
            int row = ch >> 4, c = ch & 15;
            cpa16(&Vd[row * 72 + c * 4], Vb_g + (size_t)(t0 + row) * DKK + c * 4);
        }
        cp_commit();
    };

    load_stage(0, 0);

    for (int it = 0; it < 16; it++) {
        int buf = it & 1;
        cp_wait<0>();
        __syncthreads();
        if (it + 1 < 16) load_stage(buf ^ 1, (it + 1) * 64);
        const float* Pd = Ps + buf * 128 * 68;
        const float* Vd = Vs + buf * 64 * 72;
        #pragma unroll
        for (int ks = 0; ks < 8; ks++) {
            unsigned af[2][4], bf[4][2];
            #pragma unroll
            for (int mi = 0; mi < 2; mi++) {
                int r = wm + mi * 16;
                af[mi][0] = f2tf(Pd[(r + g    ) * 68 + ks * 8 + t4]);
                af[mi][1] = f2tf(Pd[(r + g + 8) * 68 + ks * 8 + t4]);
                af[mi][2] = f2tf(Pd[(r + g    ) * 68 + ks * 8 + t4 + 4]);
                af[mi][3] = f2tf(Pd[(r + g + 8) * 68 + ks * 8 + t4 + 4]);
            }
            #pragma unroll
            for (int ni = 0; ni < 4; ni++) {
                int c = wn + ni * 8 + g;
                bf[ni][0] = f2tf(Vd[(ks * 8 + t4    ) * 72 + c]);
                bf[ni][1] = f2tf(Vd[(ks * 8 + t4 + 4) * 72 + c]);
            }
            #pragma unroll
            for (int mi = 0; mi < 2; mi++)
                #pragma unroll
                for (int ni = 0; ni < 4; ni++)
                    mma8(acc[mi][ni], af[mi], bf[ni], acc[mi][ni]);
        }
        __syncthreads();
    }

    #pragma unroll
    for (int mi = 0; mi < 2; mi++)
        #pragma unroll
        for (int ni = 0; ni < 4; ni++) {
            int qq = q0 + wm + mi * 16 + g;
            int d  = wn + ni * 8 + 2 * t4;
            *(float2*)&O[((size_t)b_ * TT + qq) * FF + h * DKK + d] =
                make_float2(acc[mi][ni][0], acc[mi][ni][1]);
            *(float2*)&O[((size_t)b_ * TT + qq + 8) * FF + h * DKK + d] =
                make_float2(acc[mi][ni][2], acc[mi][ni][3]);
        }
}

// ---------------- launch ------------------------------------------------------
extern "C" void kernel_launch(void* const* d_in, const int* in_sizes, int n_in,
                              void* d_out, int out_size)
{
    (void)in_sizes; (void)n_in; (void)out_size;
    const float* x     = (const float*)d_in[0];
    const float* q_in  = (const float*)d_in[1];
    const float* pos_k = (const float*)d_in[2];
    const int*   mask  = (const int*)  d_in[3];
    const float* ln_g  = (const float*)d_in[4];
    const float* ln_b  = (const float*)d_in[5];
    const float* Wq    = (const float*)d_in[6];
    const float* bq    = (const float*)d_in[7];
    const float* Wk    = (const float*)d_in[8];
    const float* bk    = (const float*)d_in[9];
    const float* Wv    = (const float*)d_in[10];
    const float* bv    = (const float*)d_in[11];
    const float* Wo    = (const float*)d_in[12];
    const float* bo    = (const float*)d_in[13];
    float* out = (float*)d_out;

    float *p_xn, *p_q, *p_k, *p_v, *p_s, *p_att;
    cudaGetSymbolAddress((void**)&p_xn,  g_xn);
    cudaGetSymbolAddress((void**)&p_q,   g_q);
    cudaGetSymbolAddress((void**)&p_k,   g_k);
    cudaGetSymbolAddress((void**)&p_v,   g_v);
    cudaGetSymbolAddress((void**)&p_s,   g_s);
    cudaGetSymbolAddress((void**)&p_att, g_att);

    static const int GEMM_SMEM = 3 * G_STAGE_F * 4;                        // 82944
    static const int QK_SMEM   = 2 * 128 * 68 * 4;                         // 69632
    static const int BSM_SMEM  = (32 * 1026 + 32 * 68 + 2 * 128 * 68) * 4; // 209664
    static const int AV_SMEM   = (2 * 128 * 68 + 2 * 64 * 72) * 4;         // 106496
    cudaFuncSetAttribute(proj3_kernel,    cudaFuncAttributeMaxDynamicSharedMemorySize, GEMM_SMEM);
    cudaFuncSetAttribute(gemm_out_kernel, cudaFuncAttributeMaxDynamicSharedMemorySize, GEMM_SMEM);
    cudaFuncSetAttribute(qk_tf32,         cudaFuncAttributeMaxDynamicSharedMemorySize, QK_SMEM);
    cudaFuncSetAttribute(bsm_kernel,      cudaFuncAttributeMaxDynamicSharedMemorySize, BSM_SMEM);
    cudaFuncSetAttribute(av_tf32,         cudaFuncAttributeMaxDynamicSharedMemorySize, AV_SMEM);

    ln_kernel<<<NROWS, 256>>>(x, ln_g, ln_b, p_xn);

    dim3 gproj(FF / 64, NROWS / 128, 3);   // (4, 64, 3) = 768 CTAs
    proj3_kernel<<<gproj, 256, GEMM_SMEM>>>(q_in, p_xn, Wq, bq, Wk, bk, Wv, bv,
                                            p_q, p_k, p_v);

    dim3 gqk(TT / 128, TT / 128, BHH);
    qk_tf32<<<gqk, 256, QK_SMEM>>>(p_q, p_k, p_s);

    bsm_kernel<<<TT, 512, BSM_SMEM>>>(p_q, pos_k, mask, p_s);

    dim3 gav(TT / 128, BHH);
    av_tf32<<<gav, 256, AV_SMEM>>>(p_s, p_v, p_att);

    dim3 gout(FF / 64, NROWS / 128);
    gemm_out_kernel<<<gout, 256, GEMM_SMEM>>>(p_att, Wo, bo, out);
}